// round 1
// baseline (speedup 1.0000x reference)
#include <cuda_runtime.h>
#include <math.h>

// Problem constants
// B=8, M=256, E=128, K=16, H=1024, A=256, R=1024, RMS=512
#define NEGV (-1e25f)

// ---------------- scratch (device globals; no allocation allowed) ----------------
__device__ float g_Yv[2048 * 256];     // mention gate pre-activations (V)
__device__ float g_Yu[2048 * 256];     // mention gate pre-activations (U)
__device__ float g_scores[2048];       // per-mention attention logit
__device__ float g_cat[1024 * 1536];   // [B*E, H + RMS]: cols 0..1023 = entity_reprs, 1024.. = s2
__device__ float g_sw[1024 * 1024];    // s_w = RM @ Wr^T + br   [R, H]
__device__ float g_s1[1024 * 1024];    // entity_reprs @ s_w^T   [B*E, R]
__device__ float g_RMT[512 * 1024];    // relation_memory transposed [RMS, R]

// ---------------- generic NT GEMM: C[M,N] = A[M,K] @ B[N,K]^T (+ bias[N]) --------
// Tiles: 64x64, BK=16, 256 threads, 4x4 per thread. All dims multiples of 64/16.
__global__ void gemm_nt_kernel(const float* __restrict__ A, const float* __restrict__ B,
                               float* __restrict__ C, const float* __restrict__ bias,
                               int K, int lda, int ldb, int ldc)
{
    __shared__ float As[16 * 64];
    __shared__ float Bs[16 * 64];
    const int tid = threadIdx.x;
    const int tx = tid & 15;          // 0..15 (cols)
    const int ty = tid >> 4;          // 0..15 (rows)
    const int row0 = blockIdx.y << 6;
    const int col0 = blockIdx.x << 6;
    const int lr = tid >> 2;          // 0..63
    const int lk = (tid & 3) << 2;    // 0,4,8,12

    const float* Ap = A + (size_t)(row0 + lr) * lda + lk;
    const float* Bp = B + (size_t)(col0 + lr) * ldb + lk;

    float acc[4][4] = {};

    for (int k0 = 0; k0 < K; k0 += 16) {
        float4 a4 = *(const float4*)(Ap + k0);
        float4 b4 = *(const float4*)(Bp + k0);
        As[(lk + 0) * 64 + lr] = a4.x;
        As[(lk + 1) * 64 + lr] = a4.y;
        As[(lk + 2) * 64 + lr] = a4.z;
        As[(lk + 3) * 64 + lr] = a4.w;
        Bs[(lk + 0) * 64 + lr] = b4.x;
        Bs[(lk + 1) * 64 + lr] = b4.y;
        Bs[(lk + 2) * 64 + lr] = b4.z;
        Bs[(lk + 3) * 64 + lr] = b4.w;
        __syncthreads();
#pragma unroll
        for (int kk = 0; kk < 16; kk++) {
            float4 av = *(const float4*)&As[kk * 64 + (ty << 2)];
            float4 bv = *(const float4*)&Bs[kk * 64 + (tx << 2)];
            acc[0][0] += av.x * bv.x; acc[0][1] += av.x * bv.y; acc[0][2] += av.x * bv.z; acc[0][3] += av.x * bv.w;
            acc[1][0] += av.y * bv.x; acc[1][1] += av.y * bv.y; acc[1][2] += av.y * bv.z; acc[1][3] += av.y * bv.w;
            acc[2][0] += av.z * bv.x; acc[2][1] += av.z * bv.y; acc[2][2] += av.z * bv.z; acc[2][3] += av.z * bv.w;
            acc[3][0] += av.w * bv.x; acc[3][1] += av.w * bv.y; acc[3][2] += av.w * bv.z; acc[3][3] += av.w * bv.w;
        }
        __syncthreads();
    }

    float4 bb = make_float4(0.f, 0.f, 0.f, 0.f);
    if (bias) bb = *(const float4*)&bias[col0 + (tx << 2)];
#pragma unroll
    for (int i = 0; i < 4; i++) {
        float4 c;
        c.x = acc[i][0] + bb.x;
        c.y = acc[i][1] + bb.y;
        c.z = acc[i][2] + bb.z;
        c.w = acc[i][3] + bb.w;
        *(float4*)&C[(size_t)(row0 + (ty << 2) + i) * ldc + col0 + (tx << 2)] = c;
    }
}

// ---------------- per-mention gate score reduction -------------------------------
// scores[row] = ba + sum_a tanh(Yv[row,a]) * sigmoid(Yu[row,a]) * Wa[a]
__global__ void score_reduce_kernel(const float* __restrict__ Yv, const float* __restrict__ Yu,
                                    const float* __restrict__ Wa, const float* __restrict__ ba,
                                    float* __restrict__ scores)
{
    const int row = blockIdx.x;   // 0..2047
    const int a = threadIdx.x;    // 0..255
    float v = tanhf(Yv[row * 256 + a]);
    float u = 1.f / (1.f + expf(-Yu[row * 256 + a]));
    float c = v * u * Wa[a];

    __shared__ float wsum[8];
#pragma unroll
    for (int o = 16; o > 0; o >>= 1) c += __shfl_down_sync(0xffffffffu, c, o);
    if ((a & 31) == 0) wsum[a >> 5] = c;
    __syncthreads();
    if (a == 0) {
        float s = 0.f;
#pragma unroll
        for (int i = 0; i < 8; i++) s += wsum[i];
        scores[row] = s + ba[0];
    }
}

// ---------------- masked softmax over K + weighted pooling -----------------------
// Writes entity_reprs into g_cat columns [0,1024) with row stride 1536.
__global__ void attn_pool_kernel(const float* __restrict__ X, const int* __restrict__ ent,
                                 const int* __restrict__ msk, const float* __restrict__ scores,
                                 float* __restrict__ cat)
{
    const int be = blockIdx.x;    // 0..1023  (b*128 + e)
    const int b = be >> 7;
    const int tid = threadIdx.x;  // 256 threads

    __shared__ int sidx[16];
    __shared__ float w[16];

    if (tid < 16) {
        int idx = ent[be * 16 + tid];
        int m = msk[be * 16 + tid];
        sidx[tid] = idx;
        w[tid] = m ? scores[b * 256 + idx] : NEGV;
    }
    __syncthreads();
    if (tid == 0) {
        float mx = w[0];
#pragma unroll
        for (int k = 1; k < 16; k++) mx = fmaxf(mx, w[k]);
        float e[16];
        float sum = 0.f;
#pragma unroll
        for (int k = 0; k < 16; k++) { e[k] = expf(w[k] - mx); sum += e[k]; }
        float inv = 1.f / sum;
#pragma unroll
        for (int k = 0; k < 16; k++) w[k] = e[k] * inv;
    }
    __syncthreads();

    float4 acc = make_float4(0.f, 0.f, 0.f, 0.f);
    const float4* Xb = (const float4*)(X + (size_t)b * 256 * 1024);
#pragma unroll
    for (int k = 0; k < 16; k++) {
        float wk = w[k];
        float4 x = Xb[sidx[k] * 256 + tid];
        acc.x += wk * x.x; acc.y += wk * x.y; acc.z += wk * x.z; acc.w += wk * x.w;
    }
    *(float4*)&cat[(size_t)be * 1536 + tid * 4] = acc;
}

// ---------------- transpose relation_memory [1024,512] -> [512,1024] -------------
__global__ void transpose_kernel(const float* __restrict__ RM, float* __restrict__ RMT)
{
    __shared__ float tile[32][33];
    int x = blockIdx.x * 32 + threadIdx.x;  // col in RM (0..511)
    int y = blockIdx.y * 32 + threadIdx.y;  // row in RM
#pragma unroll
    for (int j = 0; j < 32; j += 8)
        tile[threadIdx.y + j][threadIdx.x] = RM[(size_t)(y + j) * 512 + x];
    __syncthreads();
    int ox = blockIdx.y * 32 + threadIdx.x; // col in RMT (r-dim)
    int oy = blockIdx.x * 32 + threadIdx.y; // row in RMT (m-dim)
#pragma unroll
    for (int j = 0; j < 32; j += 8)
        RMT[(size_t)(oy + j) * 1024 + ox] = tile[threadIdx.x][threadIdx.y + j];
}

// ---------------- launch ---------------------------------------------------------
extern "C" void kernel_launch(void* const* d_in, const int* in_sizes, int n_in,
                              void* d_out, int out_size)
{
    const float* X   = (const float*)d_in[0];   // mention_reprs [8,256,1024]
    const int*   ent = (const int*)d_in[1];     // entities [8,128,16]
    const int*   msk = (const int*)d_in[2];     // entity_masks
    const float* RM  = (const float*)d_in[3];   // relation_memory [1024,512]
    const float* Wv  = (const float*)d_in[4];
    const float* bv  = (const float*)d_in[5];
    const float* Wu  = (const float*)d_in[6];
    const float* bu  = (const float*)d_in[7];
    const float* Wa  = (const float*)d_in[8];
    const float* ba  = (const float*)d_in[9];
    const float* Wr  = (const float*)d_in[10];  // [1024,512]
    const float* br  = (const float*)d_in[11];
    const float* Wo  = (const float*)d_in[12];  // [1024,1536]
    const float* bo  = (const float*)d_in[13];
    float* out = (float*)d_out;

    float *Yv, *Yu, *scores, *cat, *sw, *s1, *rmt;
    cudaGetSymbolAddress((void**)&Yv, g_Yv);
    cudaGetSymbolAddress((void**)&Yu, g_Yu);
    cudaGetSymbolAddress((void**)&scores, g_scores);
    cudaGetSymbolAddress((void**)&cat, g_cat);
    cudaGetSymbolAddress((void**)&sw, g_sw);
    cudaGetSymbolAddress((void**)&s1, g_s1);
    cudaGetSymbolAddress((void**)&rmt, g_RMT);

    // 1) Per-mention gate pre-activations: Yv/Yu [2048,256] = X @ {Wv,Wu}^T + {bv,bu}
    gemm_nt_kernel<<<dim3(4, 32), 256>>>(X, Wv, Yv, bv, 1024, 1024, 1024, 256);
    gemm_nt_kernel<<<dim3(4, 32), 256>>>(X, Wu, Yu, bu, 1024, 1024, 1024, 256);

    // 2) Per-mention attention logit
    score_reduce_kernel<<<2048, 256>>>(Yv, Yu, Wa, ba, scores);

    // 3) Masked softmax over K + weighted pooling -> entity_reprs (into g_cat[:, :1024])
    attn_pool_kernel<<<1024, 256>>>(X, ent, msk, scores, cat);

    // 4) RM^T for the second memory GEMM
    transpose_kernel<<<dim3(16, 32), dim3(32, 8)>>>(RM, rmt);

    // 5) s_w [R=1024, H=1024] = RM[1024,512] @ Wr[1024,512]^T + br
    gemm_nt_kernel<<<dim3(16, 16), 256>>>(RM, Wr, sw, br, 512, 512, 512, 1024);

    // 6) s1 [BE=1024, R=1024] = entity_reprs @ s_w^T   (A = g_cat with lda=1536)
    gemm_nt_kernel<<<dim3(16, 16), 256>>>(cat, sw, s1, nullptr, 1024, 1536, 1024, 1024);

    // 7) s2 [BE, RMS=512] = s1 @ RM = s1 @ RMT^T, written into g_cat[:, 1024:]
    gemm_nt_kernel<<<dim3(8, 16), 256>>>(s1, rmt, cat + 1024, nullptr, 1024, 1024, 1024, 1536);

    // 8) out [BE, H] = concat(entity_reprs, s2) @ Wo^T + bo
    gemm_nt_kernel<<<dim3(16, 16), 256>>>(cat, Wo, out, bo, 1536, 1536, 1536, 1024);
}